// round 5
// baseline (speedup 1.0000x reference)
#include <cuda_runtime.h>
#include <cstddef>

// Problem constants
#define BATCH   16
#define CIN     256
#define HH      32
#define WW      32
#define NPIX    1024          // 32*32
#define HEADS   8
#define DH      64
#define INNER   512           // HEADS*DH
#define MQKV    1536          // 512 q + 512 k + 512 v rows
#define OUT_ELEMS   (BATCH * CIN * NPIX)            // 4194304
#define ATTN_ELEMS  (BATCH * HEADS * NPIX * 9)      // 1179648

// Scratch (device globals: allocation-free rule)
__device__ float g_qkv[(size_t)BATCH * MQKV * NPIX];   // [b][1536][1024]  q|k|v
__device__ float g_ctx[(size_t)BATCH * INNER * NPIX];  // [b][512][1024]

// ---------------------------------------------------------------------------
// Batched SGEMM: C[b][m][p] = sum_k A[m][k] * B[b][k][p]  (+ bias[m])
// A row-major [M,K]; A row block selected from A1 (rows < asplit) or A2.
// B batch stride = K*1024, C batch stride = M*1024.
// Tile: 128x128, BK=16, 256 threads, 8x8 per thread (2x2 quadrants of 4x4).
// ---------------------------------------------------------------------------
#define BM 128
#define BN 128
#define BK 16

__global__ void __launch_bounds__(256, 2)
sgemm_batched(const float* __restrict__ A1, const float* __restrict__ A2, int asplit,
              const float* __restrict__ Bext, int b_use_ctx,
              float* __restrict__ Cext, int c_use_qkv,
              const float* __restrict__ bias,
              int M, int K)
{
    const int n0 = blockIdx.x * BN;
    const int m0 = blockIdx.y * BM;
    const int z  = blockIdx.z;

    const float* __restrict__ Bg = b_use_ctx ? g_ctx : Bext;
    float* __restrict__ Cg       = c_use_qkv ? g_qkv : Cext;

    const float* __restrict__ A =
        (m0 < asplit) ? (A1 + (size_t)m0 * K) : (A2 + (size_t)(m0 - asplit) * K);
    const float* __restrict__ B = Bg + (size_t)z * K * NPIX + n0;
    float* __restrict__ C = Cg + (size_t)z * M * NPIX + (size_t)m0 * NPIX + n0;

    __shared__ float As[BK][BM];
    __shared__ float Bs[BK][BN];

    const int tid = threadIdx.x;
    const int tx = tid & 15;      // 0..15 -> col groups
    const int ty = tid >> 4;      // 0..15 -> row groups

    float acc[2][2][4][4];
    #pragma unroll
    for (int a = 0; a < 2; a++)
        #pragma unroll
        for (int bq = 0; bq < 2; bq++)
            #pragma unroll
            for (int i = 0; i < 4; i++)
                #pragma unroll
                for (int j = 0; j < 4; j++)
                    acc[a][bq][i][j] = 0.f;

    for (int k0 = 0; k0 < K; k0 += BK) {
        // Load A tile (128 rows x 16 k), transpose into As[k][m]
        #pragma unroll
        for (int it = 0; it < 2; it++) {
            int fid = tid + it * 256;        // 0..511
            int row = fid >> 2;              // 0..127
            int kq  = (fid & 3) * 4;
            float4 v = *(const float4*)(A + (size_t)row * K + k0 + kq);
            As[kq + 0][row] = v.x;
            As[kq + 1][row] = v.y;
            As[kq + 2][row] = v.z;
            As[kq + 3][row] = v.w;
        }
        // Load B tile (16 k x 128 n), direct
        #pragma unroll
        for (int it = 0; it < 2; it++) {
            int fid = tid + it * 256;
            int kr  = fid >> 5;              // 0..15
            int nq  = (fid & 31) * 4;
            *(float4*)(&Bs[kr][nq]) =
                *(const float4*)(B + (size_t)(k0 + kr) * NPIX + nq);
        }
        __syncthreads();

        #pragma unroll
        for (int k = 0; k < BK; k++) {
            float4 a0 = *(const float4*)(&As[k][ty * 4]);
            float4 a1 = *(const float4*)(&As[k][64 + ty * 4]);
            float4 b0 = *(const float4*)(&Bs[k][tx * 4]);
            float4 b1 = *(const float4*)(&Bs[k][64 + tx * 4]);
            float av[2][4] = {{a0.x, a0.y, a0.z, a0.w}, {a1.x, a1.y, a1.z, a1.w}};
            float bv[2][4] = {{b0.x, b0.y, b0.z, b0.w}, {b1.x, b1.y, b1.z, b1.w}};
            #pragma unroll
            for (int mi = 0; mi < 2; mi++)
                #pragma unroll
                for (int i = 0; i < 4; i++)
                    #pragma unroll
                    for (int ni = 0; ni < 2; ni++)
                        #pragma unroll
                        for (int j = 0; j < 4; j++)
                            acc[mi][ni][i][j] += av[mi][i] * bv[ni][j];
        }
        __syncthreads();
    }

    // Epilogue
    #pragma unroll
    for (int mi = 0; mi < 2; mi++) {
        #pragma unroll
        for (int i = 0; i < 4; i++) {
            int m = mi * 64 + ty * 4 + i;
            float bvv = bias ? bias[m0 + m] : 0.f;
            #pragma unroll
            for (int ni = 0; ni < 2; ni++) {
                float4 r;
                r.x = acc[mi][ni][i][0] + bvv;
                r.y = acc[mi][ni][i][1] + bvv;
                r.z = acc[mi][ni][i][2] + bvv;
                r.w = acc[mi][ni][i][3] + bvv;
                *(float4*)(C + (size_t)m * NPIX + ni * 64 + tx * 4) = r;
            }
        }
    }
}

// ---------------------------------------------------------------------------
// 3x3 windowed attention. One thread per pixel; grid (NPIX/256, HEADS, BATCH).
// Zero-padded OOB windows: logit = 0 (k padded with zeros), v contributes 0,
// softmax runs over all 9 positions. attn written to d_out tail region.
// ---------------------------------------------------------------------------
__global__ void __launch_bounds__(256)
attn_kernel(float* __restrict__ attn_out)
{
    const int tid = threadIdx.x;
    const int p = blockIdx.x * 256 + tid;
    const int h = blockIdx.y;
    const int b = blockIdx.z;
    const int y = p >> 5;
    const int x = p & 31;

    const float* __restrict__ qb = g_qkv + ((size_t)b * MQKV + h * DH) * NPIX;
    const float* __restrict__ kb = g_qkv + ((size_t)b * MQKV + 512 + h * DH) * NPIX;
    const float* __restrict__ vb = g_qkv + ((size_t)b * MQKV + 1024 + h * DH) * NPIX;

    int  np[9];
    bool val[9];
    #pragma unroll
    for (int w = 0; w < 9; w++) {
        int dy = w / 3 - 1, dx = w % 3 - 1;
        int yy = y + dy, xx = x + dx;
        val[w] = ((unsigned)yy < 32u) && ((unsigned)xx < 32u);
        np[w]  = val[w] ? (yy * 32 + xx) : p;
    }

    float dots[9];
    #pragma unroll
    for (int w = 0; w < 9; w++) dots[w] = 0.f;

    #pragma unroll 4
    for (int d = 0; d < DH; d++) {
        float qd = qb[(size_t)d * NPIX + p];
        const float* __restrict__ kr = kb + (size_t)d * NPIX;
        #pragma unroll
        for (int w = 0; w < 9; w++)
            if (val[w]) dots[w] += qd * kr[np[w]];
    }

    // softmax over 9 (OOB logits are exactly 0, matching zero-padded k)
    const float scale = 0.125f;   // 64^-0.5
    float s[9], mx = -1e30f;
    #pragma unroll
    for (int w = 0; w < 9; w++) { s[w] = dots[w] * scale; mx = fmaxf(mx, s[w]); }
    float a[9], sum = 0.f;
    #pragma unroll
    for (int w = 0; w < 9; w++) { a[w] = expf(s[w] - mx); sum += a[w]; }
    float inv = 1.f / sum;
    #pragma unroll
    for (int w = 0; w < 9; w++) a[w] *= inv;

    // emit attn [b, h, n, 9]
    float* ao = attn_out + ((size_t)(b * HEADS + h) * NPIX + p) * 9;
    #pragma unroll
    for (int w = 0; w < 9; w++) ao[w] = a[w];

    // context: ctx[b][h*64+d][p] = sum_w a[w] * v[d][np[w]]
    float* __restrict__ cb = g_ctx + ((size_t)b * INNER + h * DH) * NPIX;
    #pragma unroll 4
    for (int d = 0; d < DH; d++) {
        const float* __restrict__ vr = vb + (size_t)d * NPIX;
        float accum = 0.f;
        #pragma unroll
        for (int w = 0; w < 9; w++)
            if (val[w]) accum += a[w] * vr[np[w]];
        cb[(size_t)d * NPIX + p] = accum;
    }
}

// ---------------------------------------------------------------------------
extern "C" void kernel_launch(void* const* d_in, const int* in_sizes, int n_in,
                              void* d_out, int out_size)
{
    const float* x   = (const float*)d_in[0];   // [16,256,32,32]
    const float* Wq  = (const float*)d_in[1];   // [512,256]
    const float* Wkv = (const float*)d_in[2];   // [1024,256]
    const float* Wo  = (const float*)d_in[3];   // [256,512]
    const float* bo  = (const float*)d_in[4];   // [256]
    float* out = (float*)d_out;                 // out (4194304) | attn (1179648)

    // 1) QKV projection: g_qkv[b][m][p] = concat(Wq,Wkv)[m] . x[b][:,p]
    {
        dim3 grid(NPIX / BN, MQKV / BM, BATCH);  // (8, 12, 16)
        sgemm_batched<<<grid, 256>>>(Wq, Wkv, 512,
                                     x, /*b_use_ctx=*/0,
                                     nullptr, /*c_use_qkv=*/1,
                                     nullptr, MQKV, CIN);
    }

    // 2) windowed attention -> g_ctx, attn -> out tail
    {
        dim3 grid(NPIX / 256, HEADS, BATCH);     // (4, 8, 16)
        attn_kernel<<<grid, 256>>>(out + OUT_ELEMS);
    }

    // 3) output projection + bias: out[b][c][p] = Wo[c] . ctx[b][:,p] + bo[c]
    {
        dim3 grid(NPIX / BN, CIN / BM, BATCH);   // (8, 2, 16)
        sgemm_batched<<<grid, 256>>>(Wo, Wo, 1 << 30,
                                     nullptr, /*b_use_ctx=*/1,
                                     out, /*c_use_qkv=*/0,
                                     bo, CIN, INNER);
    }
}

// round 6
// speedup vs baseline: 1.5180x; 1.5180x over previous
#include <cuda_runtime.h>
#include <cstddef>
#include <cstdint>

// Problem constants
#define BATCH   16
#define CIN     256
#define NPIX    1024
#define HEADS   8
#define DH      64
#define INNER   512
#define MQKV    1536
#define OUT_ELEMS   (BATCH * CIN * NPIX)            // 4194304

// Scratch (device globals: allocation-free rule)
__device__ float g_qkv[(size_t)BATCH * MQKV * NPIX];   // [b][1536][1024]  q|k|v
__device__ float g_ctx[(size_t)BATCH * INNER * NPIX];  // [b][512][1024]

// ---------------------------------------------------------------------------
// TF32 tensor-core batched GEMM: C[b][m][p] = sum_k A[m][k] * B[b][k][p] (+bias)
// Tile 128x128, BK=32. 256 threads = 8 warps as 4(m) x 2(n); warp tile 32x64.
// mma.sync.aligned.m16n8k8.row.col.f32.tf32.tf32.f32
// Smem row stride 136 floats: conflict-free fragment LDS and tile STS.
// ---------------------------------------------------------------------------
#define BM 128
#define BN 128
#define BK 32
#define SA 136
#define SB 136

__device__ __forceinline__ uint32_t f2tf32(float f) {
    uint32_t u;
    asm("cvt.rna.tf32.f32 %0, %1;" : "=r"(u) : "f"(f));
    return u;
}

__device__ __forceinline__ void mma_tf32(float c[4], const uint32_t a[4], const uint32_t b[2]) {
    asm volatile(
        "mma.sync.aligned.m16n8k8.row.col.f32.tf32.tf32.f32 "
        "{%0,%1,%2,%3},{%4,%5,%6,%7},{%8,%9},{%0,%1,%2,%3};"
        : "+f"(c[0]), "+f"(c[1]), "+f"(c[2]), "+f"(c[3])
        : "r"(a[0]), "r"(a[1]), "r"(a[2]), "r"(a[3]), "r"(b[0]), "r"(b[1]));
}

__global__ void __launch_bounds__(256, 2)
gemm_tf32(const float* __restrict__ A1, const float* __restrict__ A2, int asplit,
          const float* __restrict__ Bext, int b_use_ctx,
          float* __restrict__ Cext, int c_use_qkv,
          const float* __restrict__ bias,
          int M, int K)
{
    __shared__ uint32_t As[BK][SA];   // [k][m], tf32 bits
    __shared__ uint32_t Bs[BK][SB];   // [k][n], tf32 bits

    const int n0 = blockIdx.x * BN;
    const int m0 = blockIdx.y * BM;
    const int z  = blockIdx.z;

    const float* __restrict__ Bg = b_use_ctx ? g_ctx : Bext;
    float* __restrict__ Cg       = c_use_qkv ? g_qkv : Cext;

    const float* __restrict__ A =
        (m0 < asplit) ? (A1 + (size_t)m0 * K) : (A2 + (size_t)(m0 - asplit) * K);
    const float* __restrict__ B = Bg + (size_t)z * K * NPIX + n0;
    float* __restrict__ C = Cg + (size_t)z * M * NPIX + (size_t)m0 * NPIX + n0;

    const int tid  = threadIdx.x;
    const int lane = tid & 31;
    const int warp = tid >> 5;
    const int wm0  = (warp >> 1) * 32;   // warp m-origin within tile
    const int wn0  = (warp & 1) * 64;    // warp n-origin within tile
    const int grp  = lane >> 2;          // 0..7
    const int qid  = lane & 3;           // 0..3

    float acc[2][8][4];
    #pragma unroll
    for (int mt = 0; mt < 2; mt++)
        #pragma unroll
        for (int j = 0; j < 8; j++)
            #pragma unroll
            for (int e = 0; e < 4; e++)
                acc[mt][j][e] = 0.f;

    for (int k0 = 0; k0 < K; k0 += BK) {
        // --- Stage A tile (128 m x 32 k), transposed to As[k][m], tf32-rounded.
        // fid layout: row = fid&127 (lane-consecutive -> conflict-free STS),
        // kq = 4*(fid>>7).
        #pragma unroll
        for (int it = 0; it < 4; it++) {
            int fid = tid + it * 256;
            int kq  = (fid >> 7) * 4;
            int row = fid & 127;
            float4 v = *(const float4*)(A + (size_t)row * K + k0 + kq);
            As[kq + 0][row] = f2tf32(v.x);
            As[kq + 1][row] = f2tf32(v.y);
            As[kq + 2][row] = f2tf32(v.z);
            As[kq + 3][row] = f2tf32(v.w);
        }
        // --- Stage B tile (32 k x 128 n), direct, tf32-rounded.
        #pragma unroll
        for (int it = 0; it < 4; it++) {
            int fid = tid + it * 256;
            int kr  = fid >> 5;
            int nq  = (fid & 31) * 4;
            float4 v = *(const float4*)(B + (size_t)(k0 + kr) * NPIX + nq);
            uint4 t;
            t.x = f2tf32(v.x); t.y = f2tf32(v.y);
            t.z = f2tf32(v.z); t.w = f2tf32(v.w);
            *(uint4*)(&Bs[kr][nq]) = t;
        }
        __syncthreads();

        #pragma unroll
        for (int ks = 0; ks < 4; ks++) {
            const int kb = ks * 8 + qid;
            uint32_t afr[2][4];
            uint32_t bfr[8][2];
            #pragma unroll
            for (int mt = 0; mt < 2; mt++) {
                int mm = wm0 + mt * 16 + grp;
                afr[mt][0] = As[kb][mm];
                afr[mt][1] = As[kb][mm + 8];
                afr[mt][2] = As[kb + 4][mm];
                afr[mt][3] = As[kb + 4][mm + 8];
            }
            #pragma unroll
            for (int j = 0; j < 8; j++) {
                int nn = wn0 + j * 8 + grp;
                bfr[j][0] = Bs[kb][nn];
                bfr[j][1] = Bs[kb + 4][nn];
            }
            #pragma unroll
            for (int mt = 0; mt < 2; mt++)
                #pragma unroll
                for (int j = 0; j < 8; j++)
                    mma_tf32(acc[mt][j], afr[mt], bfr[j]);
        }
        __syncthreads();
    }

    // Epilogue: c0,c1 contiguous -> float2 stores.
    #pragma unroll
    for (int mt = 0; mt < 2; mt++) {
        #pragma unroll
        for (int e2 = 0; e2 < 2; e2++) {
            int mloc = wm0 + mt * 16 + grp + e2 * 8;
            float bv = bias ? bias[m0 + mloc] : 0.f;
            #pragma unroll
            for (int j = 0; j < 8; j++) {
                float2 r;
                r.x = acc[mt][j][e2 * 2 + 0] + bv;
                r.y = acc[mt][j][e2 * 2 + 1] + bv;
                *(float2*)(C + (size_t)mloc * NPIX + wn0 + j * 8 + 2 * qid) = r;
            }
        }
    }
}

// ---------------------------------------------------------------------------
// 3x3 windowed attention with smem halo tiling.
// Block = 256 threads covering an 8-row x 32-col pixel slab of one (b,h).
// k/v staged in d-chunks of 8 into a zero-padded 10x34 halo tile (reused
// buffer). OOB positions are 0 in the tile, matching zero-padded unfold:
// logit contribution 0, v contribution 0. Softmax over all 9 positions.
// ---------------------------------------------------------------------------
#define DCH 8          // d per chunk
#define TROWS 10       // 8 + halo
#define TCOLS 34       // 32 + halo

__global__ void __launch_bounds__(256)
attn_kernel(float* __restrict__ attn_out)
{
    __shared__ float tile[DCH][TROWS][TCOLS];   // 10.9 KB, reused for k then v

    const int tid = threadIdx.x;
    const int ry  = tid >> 5;          // 0..7 row within slab
    const int x   = tid & 31;          // 0..31
    const int r0  = blockIdx.x * 8;    // slab base row
    const int h   = blockIdx.y;
    const int b   = blockIdx.z;
    const int p   = (r0 + ry) * 32 + x;

    const float* __restrict__ qb = g_qkv + ((size_t)b * MQKV +        h * DH) * NPIX;
    const float* __restrict__ kb = g_qkv + ((size_t)b * MQKV +  512 + h * DH) * NPIX;
    const float* __restrict__ vb = g_qkv + ((size_t)b * MQKV + 1024 + h * DH) * NPIX;

    float dots[9];
    #pragma unroll
    for (int w = 0; w < 9; w++) dots[w] = 0.f;

    // Pass 1: q.k dots
    for (int dc = 0; dc < DH; dc += DCH) {
        // cooperative halo load (zero-fill OOB)
        for (int i = tid; i < DCH * TROWS * TCOLS; i += 256) {
            int d  = i / (TROWS * TCOLS);
            int rm = i % (TROWS * TCOLS);
            int rr = rm / TCOLS;
            int cc = rm % TCOLS;
            int gy = r0 + rr - 1;
            int gx = cc - 1;
            float v = 0.f;
            if ((unsigned)gy < 32u && (unsigned)gx < 32u)
                v = kb[(size_t)(dc + d) * NPIX + gy * 32 + gx];
            tile[d][rr][cc] = v;
        }
        __syncthreads();
        #pragma unroll
        for (int dd = 0; dd < DCH; dd++) {
            float qd = qb[(size_t)(dc + dd) * NPIX + p];
            #pragma unroll
            for (int w = 0; w < 9; w++)
                dots[w] += qd * tile[dd][ry + w / 3][x + w % 3];
        }
        __syncthreads();
    }

    // softmax over 9 (OOB logits exactly 0)
    const float scale = 0.125f;
    float mx = -1e30f;
    #pragma unroll
    for (int w = 0; w < 9; w++) { dots[w] *= scale; mx = fmaxf(mx, dots[w]); }
    float a[9], sum = 0.f;
    #pragma unroll
    for (int w = 0; w < 9; w++) { a[w] = expf(dots[w] - mx); sum += a[w]; }
    float inv = 1.f / sum;
    #pragma unroll
    for (int w = 0; w < 9; w++) a[w] *= inv;

    // emit attn [b, h, n, 9]
    {
        float* ao = attn_out + ((size_t)(b * HEADS + h) * NPIX + p) * 9;
        #pragma unroll
        for (int w = 0; w < 9; w++) ao[w] = a[w];
    }

    // Pass 2: ctx = attn . v
    float* __restrict__ cb = g_ctx + ((size_t)b * INNER + h * DH) * NPIX;
    for (int dc = 0; dc < DH; dc += DCH) {
        for (int i = tid; i < DCH * TROWS * TCOLS; i += 256) {
            int d  = i / (TROWS * TCOLS);
            int rm = i % (TROWS * TCOLS);
            int rr = rm / TCOLS;
            int cc = rm % TCOLS;
            int gy = r0 + rr - 1;
            int gx = cc - 1;
            float v = 0.f;
            if ((unsigned)gy < 32u && (unsigned)gx < 32u)
                v = vb[(size_t)(dc + d) * NPIX + gy * 32 + gx];
            tile[d][rr][cc] = v;
        }
        __syncthreads();
        #pragma unroll
        for (int dd = 0; dd < DCH; dd++) {
            float accum = 0.f;
            #pragma unroll
            for (int w = 0; w < 9; w++)
                accum += a[w] * tile[dd][ry + w / 3][x + w % 3];
            cb[(size_t)(dc + dd) * NPIX + p] = accum;
        }
        __syncthreads();
    }
}

// ---------------------------------------------------------------------------
extern "C" void kernel_launch(void* const* d_in, const int* in_sizes, int n_in,
                              void* d_out, int out_size)
{
    const float* x   = (const float*)d_in[0];   // [16,256,32,32]
    const float* Wq  = (const float*)d_in[1];   // [512,256]
    const float* Wkv = (const float*)d_in[2];   // [1024,256]
    const float* Wo  = (const float*)d_in[3];   // [256,512]
    const float* bo  = (const float*)d_in[4];   // [256]
    float* out = (float*)d_out;                 // out (4194304) | attn (1179648)

    // 1) QKV projection: g_qkv[b][m][p] = concat(Wq,Wkv)[m] . x[b][:,p]
    {
        dim3 grid(NPIX / BN, MQKV / BM, BATCH);  // (8, 12, 16)
        gemm_tf32<<<grid, 256>>>(Wq, Wkv, 512,
                                 x, /*b_use_ctx=*/0,
                                 nullptr, /*c_use_qkv=*/1,
                                 nullptr, MQKV, CIN);
    }

    // 2) windowed attention -> g_ctx, attn -> out tail
    {
        dim3 grid(4, HEADS, BATCH);              // (4, 8, 16)
        attn_kernel<<<grid, 256>>>(out + OUT_ELEMS);
    }

    // 3) output projection + bias
    {
        dim3 grid(NPIX / BN, CIN / BM, BATCH);   // (8, 2, 16)
        gemm_tf32<<<grid, 256>>>(Wo, Wo, 1 << 30,
                                 nullptr, /*b_use_ctx=*/1,
                                 out, /*c_use_qkv=*/0,
                                 bo, CIN, INNER);
    }
}

// round 7
// speedup vs baseline: 2.0085x; 1.3231x over previous
#include <cuda_runtime.h>
#include <cstddef>
#include <cstdint>

#define BATCH   16
#define CIN     256
#define NPIX    1024
#define HEADS   8
#define DH      64
#define INNER   512
#define MQKV    1536
#define OUT_ELEMS   (BATCH * CIN * NPIX)            // 4194304

// Scratch (device globals: allocation-free rule)
__device__ float g_qkv [(size_t)BATCH * MQKV  * NPIX];   // [b][1536][1024] q|k|v (fp32)
__device__ float g_xT  [(size_t)BATCH * NPIX  * CIN ];   // [b][p][c]   tf32-rounded
__device__ float g_ctxT[(size_t)BATCH * NPIX  * INNER];  // [b][p][hd]  tf32-rounded
__device__ float g_w   [(size_t)MQKV * CIN ];            // [1536][256] tf32-rounded (Wq|Wkv)
__device__ float g_woR [(size_t)CIN  * INNER];           // [256][512]  tf32-rounded

__device__ __forceinline__ float f2tf32f(float f) {
    uint32_t u;
    asm("cvt.rna.tf32.f32 %0, %1;" : "=r"(u) : "f"(f));
    return __uint_as_float(u);
}

// ---------------------------------------------------------------------------
// Prep 1: transpose + tf32-round x: [b][c][p] -> g_xT[b][p][c]
// ---------------------------------------------------------------------------
__global__ void __launch_bounds__(256)
prep_x(const float* __restrict__ x)
{
    __shared__ float sm[32][33];
    const int b = blockIdx.z, ct = blockIdx.y, pt = blockIdx.x;
    const int t = threadIdx.x;
    const float* xb = x + ((size_t)b * CIN + ct * 32) * NPIX + pt * 32;
    const int cl = t >> 5, pl = t & 31;
    #pragma unroll
    for (int i = 0; i < 4; i++)
        sm[cl + i * 8][pl] = xb[(size_t)(cl + i * 8) * NPIX + pl];
    __syncthreads();
    float* xo = g_xT + ((size_t)b * NPIX + pt * 32) * CIN + ct * 32;
    const int pr = t >> 5, cc = t & 31;
    #pragma unroll
    for (int i = 0; i < 4; i++)
        xo[(size_t)(pr + i * 8) * CIN + cc] = f2tf32f(sm[cc][pr + i * 8]);
}

// ---------------------------------------------------------------------------
// Prep 2: round weights into g_w (Wq|Wkv) and g_woR. float4 grid-stride.
// ---------------------------------------------------------------------------
__global__ void __launch_bounds__(256)
prep_w(const float* __restrict__ Wq, const float* __restrict__ Wkv,
       const float* __restrict__ Wo)
{
    const int i = blockIdx.x * 256 + threadIdx.x;   // float4 index, grid covers 131072
    float4 v; float* dst;
    if (i < 32768)            { v = ((const float4*)Wq)[i];           dst = g_w   + (size_t)i * 4; }
    else if (i < 98304)       { v = ((const float4*)Wkv)[i - 32768];  dst = g_w   + (size_t)i * 4; }
    else                      { v = ((const float4*)Wo)[i - 98304];   dst = g_woR + (size_t)(i - 98304) * 4; }
    float4 r;
    r.x = f2tf32f(v.x); r.y = f2tf32f(v.y); r.z = f2tf32f(v.z); r.w = f2tf32f(v.w);
    *(float4*)dst = r;
}

// ---------------------------------------------------------------------------
// Pipelined TF32 tensor-core GEMM.
// C[z][m][p] = sum_k A[m][k] * B[z][n=p][k]  (+ bias[m])
// A: [M][K] row-major tf32.  B: [z][1024][K] row-major tf32 (n-major!).
// Tile 128x128x32, 2-stage cp.async double buffer, ldmatrix fragments.
// 256 threads = 8 warps (4m x 2n), warp tile 32x64.
// ---------------------------------------------------------------------------
#define BM 128
#define BN 128
#define BK 32
#define RSW 36                       // smem row stride, words (144B: 16B-aligned, conflict-free)
#define ATILE_B (128 * RSW * 4)      // 18432 bytes
#define STAGE_B (2 * ATILE_B)        // 36864 bytes (A then B)
#define SMEM_TOTAL_B (2 * STAGE_B)   // 73728 bytes

__device__ __forceinline__ void cp16(uint32_t dst, const void* src) {
    asm volatile("cp.async.cg.shared.global [%0], [%1], 16;" :: "r"(dst), "l"(src));
}
__device__ __forceinline__ void cp_commit() {
    asm volatile("cp.async.commit_group;" ::: "memory");
}
__device__ __forceinline__ void cp_wait1() {
    asm volatile("cp.async.wait_group 1;" ::: "memory");
}
__device__ __forceinline__ void ldm_x4(uint32_t r[4], uint32_t saddr) {
    asm volatile("ldmatrix.sync.aligned.m8n8.x4.shared.b16 {%0,%1,%2,%3}, [%4];"
        : "=r"(r[0]), "=r"(r[1]), "=r"(r[2]), "=r"(r[3]) : "r"(saddr));
}
__device__ __forceinline__ void mma_tf32(float c[4], const uint32_t a[4], const uint32_t b[2]) {
    asm volatile(
        "mma.sync.aligned.m16n8k8.row.col.f32.tf32.tf32.f32 "
        "{%0,%1,%2,%3},{%4,%5,%6,%7},{%8,%9},{%0,%1,%2,%3};"
        : "+f"(c[0]), "+f"(c[1]), "+f"(c[2]), "+f"(c[3])
        : "r"(a[0]), "r"(a[1]), "r"(a[2]), "r"(a[3]), "r"(b[0]), "r"(b[1]));
}

extern __shared__ uint8_t g_dsmem[];

__global__ void __launch_bounds__(256, 2)
gemm_pipe(int a_sel, int b_sel, float* __restrict__ Cext, int c_sel,
          const float* __restrict__ bias, int M, int K)
{
    const int n0 = blockIdx.x * BN;
    const int m0 = blockIdx.y * BM;
    const int z  = blockIdx.z;

    const float* __restrict__ A = (a_sel == 1) ? g_w : g_woR;
    const float* __restrict__ Bm = (b_sel == 1) ? g_xT : g_ctxT;
    float* __restrict__ C = (c_sel == 1) ? g_qkv : Cext;

    const float* __restrict__ Ab = A + (size_t)m0 * K;
    const float* __restrict__ Bb = Bm + ((size_t)z * NPIX + n0) * K;
    C += (size_t)z * M * NPIX + (size_t)m0 * NPIX + n0;

    const uint32_t sbase = (uint32_t)__cvta_generic_to_shared(g_dsmem);

    const int tid  = threadIdx.x;
    const int lane = tid & 31;
    const int warp = tid >> 5;
    const int wm0  = (warp >> 1) * 32;
    const int wn0  = (warp & 1) * 64;
    const int grp  = lane >> 2;
    const int qid  = lane & 3;

    // staging: fid -> row (0..127), 16B segment (0..7)
    const int sr  = tid >> 3;        // base row for it=0 (rows advance by 32)
    const int seg = tid & 7;

    // ldmatrix per-lane row/col offsets
    const int a_mrow = ((lane >> 3) & 1) * 8 + (lane & 7);        // within warp m-tile
    const int a_koff = ((lane >> 4) & 1) * 4;
    const int b_nrow = ((lane >> 4) & 1) * 8 + (lane & 7);        // within 16-n pair
    const int b_koff = ((lane >> 3) & 1) * 4;

    float acc[2][8][4];
    #pragma unroll
    for (int mt = 0; mt < 2; mt++)
        #pragma unroll
        for (int j = 0; j < 8; j++)
            #pragma unroll
            for (int e = 0; e < 4; e++) acc[mt][j][e] = 0.f;

    const int NT = K / BK;

    // stage kt into buffer s
    auto stage = [&](int kt, int s) {
        const uint32_t aB = sbase + s * STAGE_B;
        const uint32_t bB = aB + ATILE_B;
        const int kw = kt * BK + seg * 4;       // word offset in k
        #pragma unroll
        for (int it = 0; it < 4; it++) {
            int r = sr + it * 32;
            cp16(aB + r * (RSW * 4) + seg * 16, Ab + (size_t)r * K + kw);
            cp16(bB + r * (RSW * 4) + seg * 16, Bb + (size_t)r * K + kw);
        }
    };

    stage(0, 0);
    cp_commit();

    for (int kt = 0; kt < NT; kt++) {
        if (kt + 1 < NT) stage(kt + 1, (kt + 1) & 1);
        cp_commit();
        cp_wait1();
        __syncthreads();

        const uint32_t aS = sbase + (kt & 1) * STAGE_B;
        const uint32_t bS = aS + ATILE_B;

        #pragma unroll
        for (int ks = 0; ks < 4; ks++) {
            uint32_t afr[2][4];
            #pragma unroll
            for (int mt = 0; mt < 2; mt++)
                ldm_x4(afr[mt], aS + (wm0 + mt * 16 + a_mrow) * (RSW * 4)
                                   + (ks * 8 + a_koff) * 4);
            uint32_t bfr[8][2];
            #pragma unroll
            for (int jj = 0; jj < 4; jj++) {
                uint32_t r[4];
                ldm_x4(r, bS + (wn0 + jj * 16 + b_nrow) * (RSW * 4)
                             + (ks * 8 + b_koff) * 4);
                bfr[jj * 2 + 0][0] = r[0]; bfr[jj * 2 + 0][1] = r[1];
                bfr[jj * 2 + 1][0] = r[2]; bfr[jj * 2 + 1][1] = r[3];
            }
            #pragma unroll
            for (int mt = 0; mt < 2; mt++)
                #pragma unroll
                for (int j = 0; j < 8; j++)
                    mma_tf32(acc[mt][j], afr[mt], bfr[j]);
        }
        __syncthreads();
    }

    // Epilogue (c0,c1 contiguous in n -> float2)
    #pragma unroll
    for (int mt = 0; mt < 2; mt++) {
        #pragma unroll
        for (int e2 = 0; e2 < 2; e2++) {
            int mloc = wm0 + mt * 16 + grp + e2 * 8;
            float bv = bias ? bias[m0 + mloc] : 0.f;
            #pragma unroll
            for (int j = 0; j < 8; j++) {
                float2 r;
                r.x = acc[mt][j][e2 * 2 + 0] + bv;
                r.y = acc[mt][j][e2 * 2 + 1] + bv;
                *(float2*)(C + (size_t)mloc * NPIX + wn0 + j * 8 + 2 * qid) = r;
            }
        }
    }
}

// ---------------------------------------------------------------------------
// 3x3 windowed attention with smem halo tiling. Block = 8row x 32col pixel
// slab of one (b,h). Zero-filled halo == zero-padded unfold (OOB logit = 0).
// Emits attn [b,h,n,9] and ctx transposed + tf32-rounded: g_ctxT[b][p][h*64+d].
// ---------------------------------------------------------------------------
#define DCH 8
#define TROWS 10
#define TCOLS 34

__global__ void __launch_bounds__(256)
attn_kernel(float* __restrict__ attn_out)
{
    __shared__ float tile[DCH][TROWS][TCOLS];

    const int tid = threadIdx.x;
    const int ry  = tid >> 5;
    const int x   = tid & 31;
    const int r0  = blockIdx.x * 8;
    const int h   = blockIdx.y;
    const int b   = blockIdx.z;
    const int p   = (r0 + ry) * 32 + x;

    const float* __restrict__ qb = g_qkv + ((size_t)b * MQKV +        h * DH) * NPIX;
    const float* __restrict__ kb = g_qkv + ((size_t)b * MQKV +  512 + h * DH) * NPIX;
    const float* __restrict__ vb = g_qkv + ((size_t)b * MQKV + 1024 + h * DH) * NPIX;

    float dots[9];
    #pragma unroll
    for (int w = 0; w < 9; w++) dots[w] = 0.f;

    // Pass 1: q.k
    for (int dc = 0; dc < DH; dc += DCH) {
        for (int i = tid; i < DCH * TROWS * TCOLS; i += 256) {
            int d  = i / (TROWS * TCOLS);
            int rm = i % (TROWS * TCOLS);
            int rr = rm / TCOLS, cc = rm % TCOLS;
            int gy = r0 + rr - 1, gx = cc - 1;
            float v = 0.f;
            if ((unsigned)gy < 32u && (unsigned)gx < 32u)
                v = kb[(size_t)(dc + d) * NPIX + gy * 32 + gx];
            tile[d][rr][cc] = v;
        }
        __syncthreads();
        #pragma unroll
        for (int dd = 0; dd < DCH; dd++) {
            float qd = qb[(size_t)(dc + dd) * NPIX + p];
            #pragma unroll
            for (int w = 0; w < 9; w++)
                dots[w] += qd * tile[dd][ry + w / 3][x + w % 3];
        }
        __syncthreads();
    }

    // softmax over 9
    const float scale = 0.125f;
    float mx = -1e30f;
    #pragma unroll
    for (int w = 0; w < 9; w++) { dots[w] *= scale; mx = fmaxf(mx, dots[w]); }
    float a[9], sum = 0.f;
    #pragma unroll
    for (int w = 0; w < 9; w++) { a[w] = expf(dots[w] - mx); sum += a[w]; }
    float inv = 1.f / sum;
    #pragma unroll
    for (int w = 0; w < 9; w++) a[w] *= inv;

    {
        float* ao = attn_out + ((size_t)(b * HEADS + h) * NPIX + p) * 9;
        #pragma unroll
        for (int w = 0; w < 9; w++) ao[w] = a[w];
    }

    // Pass 2: ctx = attn.v -> transposed, tf32-rounded
    float* __restrict__ ct = g_ctxT + ((size_t)b * NPIX + p) * INNER + h * DH;
    for (int dc = 0; dc < DH; dc += DCH) {
        for (int i = tid; i < DCH * TROWS * TCOLS; i += 256) {
            int d  = i / (TROWS * TCOLS);
            int rm = i % (TROWS * TCOLS);
            int rr = rm / TCOLS, cc = rm % TCOLS;
            int gy = r0 + rr - 1, gx = cc - 1;
            float v = 0.f;
            if ((unsigned)gy < 32u && (unsigned)gx < 32u)
                v = vb[(size_t)(dc + d) * NPIX + gy * 32 + gx];
            tile[d][rr][cc] = v;
        }
        __syncthreads();
        float acc8[DCH];
        #pragma unroll
        for (int dd = 0; dd < DCH; dd++) {
            float s = 0.f;
            #pragma unroll
            for (int w = 0; w < 9; w++)
                s += a[w] * tile[dd][ry + w / 3][x + w % 3];
            acc8[dd] = f2tf32f(s);
        }
        float4 r0v = make_float4(acc8[0], acc8[1], acc8[2], acc8[3]);
        float4 r1v = make_float4(acc8[4], acc8[5], acc8[6], acc8[7]);
        *(float4*)(ct + dc)     = r0v;
        *(float4*)(ct + dc + 4) = r1v;
        __syncthreads();
    }
}

// ---------------------------------------------------------------------------
extern "C" void kernel_launch(void* const* d_in, const int* in_sizes, int n_in,
                              void* d_out, int out_size)
{
    const float* x   = (const float*)d_in[0];
    const float* Wq  = (const float*)d_in[1];
    const float* Wkv = (const float*)d_in[2];
    const float* Wo  = (const float*)d_in[3];
    const float* bo  = (const float*)d_in[4];
    float* out = (float*)d_out;     // out (4194304) | attn (1179648)

    static int smem_set = 0;
    if (!smem_set) {
        cudaFuncSetAttribute(gemm_pipe, cudaFuncAttributeMaxDynamicSharedMemorySize,
                             SMEM_TOTAL_B);
        smem_set = 1;
    }

    // prep: transpose+round x, round weights
    {
        dim3 g(32, 8, BATCH);
        prep_x<<<g, 256>>>(x);
        prep_w<<<512, 256>>>(Wq, Wkv, Wo);
    }

    // QKV: g_qkv[b][m][p] = g_w[m][:] . g_xT[b][p][:]
    {
        dim3 grid(NPIX / BN, MQKV / BM, BATCH);   // (8, 12, 16)
        gemm_pipe<<<grid, 256, SMEM_TOTAL_B>>>(1, 1, nullptr, 1, nullptr, MQKV, CIN);
    }

    // attention -> attn tail + g_ctxT
    {
        dim3 grid(4, HEADS, BATCH);
        attn_kernel<<<grid, 256>>>(out + OUT_ELEMS);
    }

    // out projection: out[b][c][p] = g_woR[c][:] . g_ctxT[b][p][:] + bo[c]
    {
        dim3 grid(NPIX / BN, CIN / BM, BATCH);    // (8, 2, 16)
        gemm_pipe<<<grid, 256, SMEM_TOTAL_B>>>(2, 2, out, 0, bo, CIN, INNER);
    }
}

// round 8
// speedup vs baseline: 2.3163x; 1.1533x over previous
#include <cuda_runtime.h>
#include <cstddef>
#include <cstdint>

#define BATCH   16
#define CIN     256
#define NPIX    1024
#define HEADS   8
#define DH      64
#define INNER   512
#define MQKV    1536
#define OUT_ELEMS   (BATCH * CIN * NPIX)            // 4194304

// Scratch (device globals: allocation-free rule)
__device__ float g_qkv [(size_t)BATCH * MQKV  * NPIX];   // [b][1536][1024] q|k|v (fp32)
__device__ float g_xT  [(size_t)BATCH * NPIX  * CIN ];   // [b][p][c]   tf32-rounded
__device__ float g_ctxT[(size_t)BATCH * NPIX  * INNER];  // [b][p][hd]  tf32-rounded
__device__ float g_w   [(size_t)MQKV * CIN ];            // [1536][256] tf32-rounded (Wq|Wkv)
__device__ float g_woR [(size_t)CIN  * INNER];           // [256][512]  tf32-rounded

__device__ __forceinline__ float f2tf32f(float f) {
    uint32_t u;
    asm("cvt.rna.tf32.f32 %0, %1;" : "=r"(u) : "f"(f));
    return __uint_as_float(u);
}

// ---------------------------------------------------------------------------
// Prep 1: transpose + tf32-round x: [b][c][p] -> g_xT[b][p][c]
// ---------------------------------------------------------------------------
__global__ void __launch_bounds__(256)
prep_x(const float* __restrict__ x)
{
    __shared__ float sm[32][33];
    const int b = blockIdx.z, ct = blockIdx.y, pt = blockIdx.x;
    const int t = threadIdx.x;
    const float* xb = x + ((size_t)b * CIN + ct * 32) * NPIX + pt * 32;
    const int cl = t >> 5, pl = t & 31;
    #pragma unroll
    for (int i = 0; i < 4; i++)
        sm[cl + i * 8][pl] = xb[(size_t)(cl + i * 8) * NPIX + pl];
    __syncthreads();
    float* xo = g_xT + ((size_t)b * NPIX + pt * 32) * CIN + ct * 32;
    const int pr = t >> 5, cc = t & 31;
    #pragma unroll
    for (int i = 0; i < 4; i++)
        xo[(size_t)(pr + i * 8) * CIN + cc] = f2tf32f(sm[cc][pr + i * 8]);
}

// ---------------------------------------------------------------------------
// Prep 2: round weights into g_w (Wq|Wkv) and g_woR. float4 grid-stride.
// ---------------------------------------------------------------------------
__global__ void __launch_bounds__(256)
prep_w(const float* __restrict__ Wq, const float* __restrict__ Wkv,
       const float* __restrict__ Wo)
{
    const int i = blockIdx.x * 256 + threadIdx.x;   // float4 index, grid covers 131072
    float4 v; float* dst;
    if (i < 32768)            { v = ((const float4*)Wq)[i];           dst = g_w   + (size_t)i * 4; }
    else if (i < 98304)       { v = ((const float4*)Wkv)[i - 32768];  dst = g_w   + (size_t)i * 4; }
    else                      { v = ((const float4*)Wo)[i - 98304];   dst = g_woR + (size_t)(i - 98304) * 4; }
    float4 r;
    r.x = f2tf32f(v.x); r.y = f2tf32f(v.y); r.z = f2tf32f(v.z); r.w = f2tf32f(v.w);
    *(float4*)dst = r;
}

// ---------------------------------------------------------------------------
// Pipelined TF32 tensor-core GEMM (unchanged from R6).
// C[z][m][p] = sum_k A[m][k] * B[z][n=p][k]  (+ bias[m])
// ---------------------------------------------------------------------------
#define BM 128
#define BN 128
#define BK 32
#define RSW 36
#define ATILE_B (128 * RSW * 4)
#define STAGE_B (2 * ATILE_B)
#define SMEM_TOTAL_B (2 * STAGE_B)

__device__ __forceinline__ void cp16(uint32_t dst, const void* src) {
    asm volatile("cp.async.cg.shared.global [%0], [%1], 16;" :: "r"(dst), "l"(src));
}
__device__ __forceinline__ void cp4z(uint32_t dst, const void* src, bool ok) {
    int sz = ok ? 4 : 0;
    asm volatile("cp.async.ca.shared.global [%0], [%1], 4, %2;"
                 :: "r"(dst), "l"(src), "r"(sz));
}
__device__ __forceinline__ void cp_commit() {
    asm volatile("cp.async.commit_group;" ::: "memory");
}
__device__ __forceinline__ void cp_wait1() {
    asm volatile("cp.async.wait_group 1;" ::: "memory");
}
__device__ __forceinline__ void cp_wait0() {
    asm volatile("cp.async.wait_group 0;" ::: "memory");
}
__device__ __forceinline__ void ldm_x4(uint32_t r[4], uint32_t saddr) {
    asm volatile("ldmatrix.sync.aligned.m8n8.x4.shared.b16 {%0,%1,%2,%3}, [%4];"
        : "=r"(r[0]), "=r"(r[1]), "=r"(r[2]), "=r"(r[3]) : "r"(saddr));
}
__device__ __forceinline__ void mma_tf32(float c[4], const uint32_t a[4], const uint32_t b[2]) {
    asm volatile(
        "mma.sync.aligned.m16n8k8.row.col.f32.tf32.tf32.f32 "
        "{%0,%1,%2,%3},{%4,%5,%6,%7},{%8,%9},{%0,%1,%2,%3};"
        : "+f"(c[0]), "+f"(c[1]), "+f"(c[2]), "+f"(c[3])
        : "r"(a[0]), "r"(a[1]), "r"(a[2]), "r"(a[3]), "r"(b[0]), "r"(b[1]));
}

extern __shared__ uint8_t g_dsmem[];

__global__ void __launch_bounds__(256, 2)
gemm_pipe(int a_sel, int b_sel, float* __restrict__ Cext, int c_sel,
          const float* __restrict__ bias, int M, int K)
{
    const int n0 = blockIdx.x * BN;
    const int m0 = blockIdx.y * BM;
    const int z  = blockIdx.z;

    const float* __restrict__ A = (a_sel == 1) ? g_w : g_woR;
    const float* __restrict__ Bm = (b_sel == 1) ? g_xT : g_ctxT;
    float* __restrict__ C = (c_sel == 1) ? g_qkv : Cext;

    const float* __restrict__ Ab = A + (size_t)m0 * K;
    const float* __restrict__ Bb = Bm + ((size_t)z * NPIX + n0) * K;
    C += (size_t)z * M * NPIX + (size_t)m0 * NPIX + n0;

    const uint32_t sbase = (uint32_t)__cvta_generic_to_shared(g_dsmem);

    const int tid  = threadIdx.x;
    const int lane = tid & 31;
    const int warp = tid >> 5;
    const int wm0  = (warp >> 1) * 32;
    const int wn0  = (warp & 1) * 64;
    const int grp  = lane >> 2;
    const int qid  = lane & 3;

    const int sr  = tid >> 3;
    const int seg = tid & 7;

    const int a_mrow = ((lane >> 3) & 1) * 8 + (lane & 7);
    const int a_koff = ((lane >> 4) & 1) * 4;
    const int b_nrow = ((lane >> 4) & 1) * 8 + (lane & 7);
    const int b_koff = ((lane >> 3) & 1) * 4;

    float acc[2][8][4];
    #pragma unroll
    for (int mt = 0; mt < 2; mt++)
        #pragma unroll
        for (int j = 0; j < 8; j++)
            #pragma unroll
            for (int e = 0; e < 4; e++) acc[mt][j][e] = 0.f;

    const int NT = K / BK;

    auto stage = [&](int kt, int s) {
        const uint32_t aB = sbase + s * STAGE_B;
        const uint32_t bB = aB + ATILE_B;
        const int kw = kt * BK + seg * 4;
        #pragma unroll
        for (int it = 0; it < 4; it++) {
            int r = sr + it * 32;
            cp16(aB + r * (RSW * 4) + seg * 16, Ab + (size_t)r * K + kw);
            cp16(bB + r * (RSW * 4) + seg * 16, Bb + (size_t)r * K + kw);
        }
    };

    stage(0, 0);
    cp_commit();

    for (int kt = 0; kt < NT; kt++) {
        if (kt + 1 < NT) stage(kt + 1, (kt + 1) & 1);
        cp_commit();
        cp_wait1();
        __syncthreads();

        const uint32_t aS = sbase + (kt & 1) * STAGE_B;
        const uint32_t bS = aS + ATILE_B;

        #pragma unroll
        for (int ks = 0; ks < 4; ks++) {
            uint32_t afr[2][4];
            #pragma unroll
            for (int mt = 0; mt < 2; mt++)
                ldm_x4(afr[mt], aS + (wm0 + mt * 16 + a_mrow) * (RSW * 4)
                                   + (ks * 8 + a_koff) * 4);
            uint32_t bfr[8][2];
            #pragma unroll
            for (int jj = 0; jj < 4; jj++) {
                uint32_t r[4];
                ldm_x4(r, bS + (wn0 + jj * 16 + b_nrow) * (RSW * 4)
                             + (ks * 8 + b_koff) * 4);
                bfr[jj * 2 + 0][0] = r[0]; bfr[jj * 2 + 0][1] = r[1];
                bfr[jj * 2 + 1][0] = r[2]; bfr[jj * 2 + 1][1] = r[3];
            }
            #pragma unroll
            for (int mt = 0; mt < 2; mt++)
                #pragma unroll
                for (int j = 0; j < 8; j++)
                    mma_tf32(acc[mt][j], afr[mt], bfr[j]);
        }
        __syncthreads();
    }

    #pragma unroll
    for (int mt = 0; mt < 2; mt++) {
        #pragma unroll
        for (int e2 = 0; e2 < 2; e2++) {
            int mloc = wm0 + mt * 16 + grp + e2 * 8;
            float bv = bias ? bias[m0 + mloc] : 0.f;
            #pragma unroll
            for (int j = 0; j < 8; j++) {
                float2 r;
                r.x = acc[mt][j][e2 * 2 + 0] + bv;
                r.y = acc[mt][j][e2 * 2 + 1] + bv;
                *(float2*)(C + (size_t)mloc * NPIX + wn0 + j * 8 + 2 * qid) = r;
            }
        }
    }
}

// ---------------------------------------------------------------------------
// 3x3 windowed attention, cp.async double-buffered halo staging, no div/mod.
// Block = 8row x 32col pixel slab of one (b,h); 8 warps, warp w stages d-plane
// (dc + w) of the 10x34 zero-padded halo tile via cp.async zfill (OOB -> 0,
// matching zero-padded unfold: OOB logit = 0, v contribution 0).
// Emits attn [b,h,n,9] and ctx transposed + tf32-rounded g_ctxT[b][p][h*64+d].
// ---------------------------------------------------------------------------
#define DCH 8
#define TROWS 10
#define TCOLS 34
#define PLANE_W (TROWS * TCOLS)          // 340 words per d-plane
#define TILE_BYTES (DCH * PLANE_W * 4)   // 10880 bytes per buffer

__global__ void __launch_bounds__(256)
attn_kernel(float* __restrict__ attn_out)
{
    __shared__ float tile[2][DCH][TROWS][TCOLS];   // 21.76 KB, double-buffered

    const int tid  = threadIdx.x;
    const int lane = tid & 31;
    const int warp = tid >> 5;
    const int ry   = warp;            // row within slab (8 warps = 8 rows)
    const int x    = lane;            // col
    const int r0   = blockIdx.x * 8;
    const int h    = blockIdx.y;
    const int b    = blockIdx.z;
    const int p    = (r0 + ry) * 32 + x;

    const float* __restrict__ qb = g_qkv + ((size_t)b * MQKV +        h * DH) * NPIX;
    const float* __restrict__ kb = g_qkv + ((size_t)b * MQKV +  512 + h * DH) * NPIX;
    const float* __restrict__ vb = g_qkv + ((size_t)b * MQKV + 1024 + h * DH) * NPIX;

    const uint32_t tb = (uint32_t)__cvta_generic_to_shared(&tile[0][0][0][0]);

    // warp stages plane (dc + warp) of buffer s; lanes cover columns, rows explicit
    auto stage = [&](const float* __restrict__ src_base, int dc, int s) {
        const float* __restrict__ src = src_base + (size_t)(dc + warp) * NPIX;
        const uint32_t dst = tb + (uint32_t)(s * TILE_BYTES + warp * (PLANE_W * 4));
        #pragma unroll
        for (int rr = 0; rr < TROWS; rr++) {
            const int gy = r0 + rr - 1;
            const bool rowok = ((unsigned)gy < 32u);
            const int gx = lane - 1;
            cp4z(dst + (rr * TCOLS + lane) * 4, src + gy * 32 + gx,
                 rowok && ((unsigned)gx < 32u));
            if (lane < 2) {
                const int gx2 = lane + 31;
                cp4z(dst + (rr * TCOLS + lane + 32) * 4, src + gy * 32 + gx2,
                     rowok && ((unsigned)gx2 < 32u));
            }
        }
    };

    // ---------------- Pass 1: dots = q . k ----------------
    float dots[9];
    #pragma unroll
    for (int w = 0; w < 9; w++) dots[w] = 0.f;

    stage(kb, 0, 0); cp_commit();
    stage(kb, DCH, 1); cp_commit();

    #pragma unroll 1
    for (int c = 0; c < DH / DCH; c++) {
        if (c == DH / DCH - 1) cp_wait0(); else cp_wait1();
        __syncthreads();
        const int s = c & 1;
        const int dc = c * DCH;
        #pragma unroll
        for (int dd = 0; dd < DCH; dd++) {
            float qd = qb[(size_t)(dc + dd) * NPIX + p];
            #pragma unroll
            for (int w = 0; w < 9; w++)
                dots[w] += qd * tile[s][dd][ry + w / 3][x + w % 3];
        }
        __syncthreads();
        if (c + 2 < DH / DCH) { stage(kb, (c + 2) * DCH, s); cp_commit(); }
    }

    // softmax over 9 (OOB logits exactly 0)
    const float scale = 0.125f;
    float mx = -1e30f;
    #pragma unroll
    for (int w = 0; w < 9; w++) { dots[w] *= scale; mx = fmaxf(mx, dots[w]); }
    float a[9], sum = 0.f;
    #pragma unroll
    for (int w = 0; w < 9; w++) { a[w] = expf(dots[w] - mx); sum += a[w]; }
    float inv = 1.f / sum;
    #pragma unroll
    for (int w = 0; w < 9; w++) a[w] *= inv;

    {
        float* ao = attn_out + ((size_t)(b * HEADS + h) * NPIX + p) * 9;
        #pragma unroll
        for (int w = 0; w < 9; w++) ao[w] = a[w];
    }

    // ---------------- Pass 2: ctx = attn . v ----------------
    float* __restrict__ ct = g_ctxT + ((size_t)b * NPIX + p) * INNER + h * DH;

    stage(vb, 0, 0); cp_commit();
    stage(vb, DCH, 1); cp_commit();

    #pragma unroll 1
    for (int c = 0; c < DH / DCH; c++) {
        if (c == DH / DCH - 1) cp_wait0(); else cp_wait1();
        __syncthreads();
        const int s = c & 1;
        const int dc = c * DCH;
        float acc8[DCH];
        #pragma unroll
        for (int dd = 0; dd < DCH; dd++) {
            float sacc = 0.f;
            #pragma unroll
            for (int w = 0; w < 9; w++)
                sacc += a[w] * tile[s][dd][ry + w / 3][x + w % 3];
            acc8[dd] = f2tf32f(sacc);
        }
        *(float4*)(ct + dc)     = make_float4(acc8[0], acc8[1], acc8[2], acc8[3]);
        *(float4*)(ct + dc + 4) = make_float4(acc8[4], acc8[5], acc8[6], acc8[7]);
        __syncthreads();
        if (c + 2 < DH / DCH) { stage(vb, (c + 2) * DCH, s); cp_commit(); }
    }
}

// ---------------------------------------------------------------------------
extern "C" void kernel_launch(void* const* d_in, const int* in_sizes, int n_in,
                              void* d_out, int out_size)
{
    const float* x   = (const float*)d_in[0];
    const float* Wq  = (const float*)d_in[1];
    const float* Wkv = (const float*)d_in[2];
    const float* Wo  = (const float*)d_in[3];
    const float* bo  = (const float*)d_in[4];
    float* out = (float*)d_out;     // out (4194304) | attn (1179648)

    static int smem_set = 0;
    if (!smem_set) {
        cudaFuncSetAttribute(gemm_pipe, cudaFuncAttributeMaxDynamicSharedMemorySize,
                             SMEM_TOTAL_B);
        smem_set = 1;
    }

    // prep: transpose+round x, round weights
    {
        dim3 g(32, 8, BATCH);
        prep_x<<<g, 256>>>(x);
        prep_w<<<512, 256>>>(Wq, Wkv, Wo);
    }

    // QKV: g_qkv[b][m][p] = g_w[m][:] . g_xT[b][p][:]
    {
        dim3 grid(NPIX / BN, MQKV / BM, BATCH);   // (8, 12, 16)
        gemm_pipe<<<grid, 256, SMEM_TOTAL_B>>>(1, 1, nullptr, 1, nullptr, MQKV, CIN);
    }

    // attention -> attn tail + g_ctxT
    {
        dim3 grid(4, HEADS, BATCH);
        attn_kernel<<<grid, 256>>>(out + OUT_ELEMS);
    }

    // out projection: out[b][c][p] = g_woR[c][:] . g_ctxT[b][p][:] + bo[c]
    {
        dim3 grid(NPIX / BN, CIN / BM, BATCH);    // (8, 2, 16)
        gemm_pipe<<<grid, 256, SMEM_TOTAL_B>>>(2, 2, out, 0, bo, CIN, INNER);
    }
}